// round 10
// baseline (speedup 1.0000x reference)
#include <cuda_runtime.h>
#include <cuda_fp16.h>
#include <math.h>
#include <stdint.h>

// Problem dims
#define SEQ    4096
#define IDIM   2048
#define HDIM   2048
#define GROWS  8192   // 4*HDIM, PyTorch gate order i,f,g,o
#define OUTD   2048

// Persistent recurrence kernel config
#define UPC      14
#define NCTA     147
#define RTHREADS 1024             // 32 warps: 4 k-groups x 8 row-groups
#define MAXROWS  (4*UPC)
#define SW_BYTES (MAXROWS*HDIM*sizeof(__half))   // 229376 B

// mma.sync GEMM config
#define BM 128
#define BN 128
#define BK 32
#define NCH    (IDIM/BK)          // 64 k-chunks
#define STAGES 4
#define APAD   40                 // halves per SMEM row (32 + 8 pad) -> 80B stride
#define STG_A  (BM*APAD*2)        // 10240 B
#define STG_B  (2*STG_A)          // 20480 B per stage (A then B)
#define GEMM_SMEM (STAGES*STG_B)  // 81920 B

// -------- device scratch (static allocation only) --------
__device__ float    g_xg[(size_t)SEQ * GROWS];   // 128 MB
__device__ __half   g_xh[(size_t)SEQ * IDIM];    // 16 MB  x in fp16
__device__ __half   g_wh[(size_t)GROWS * IDIM];  // 32 MB  W_ih in fp16
__device__ float    g_h[2][HDIM];
__device__ unsigned g_bar  = 0u;                 // monotonic arrival counter
__device__ unsigned g_base = 0u;                 // epoch base across graph replays

// ---------------- PTX helpers (all sm_80+; no arch-suffix features) ----------
__device__ __forceinline__ uint32_t smem_u32(const void* p) {
    return (uint32_t)__cvta_generic_to_shared(p);
}
__device__ __forceinline__ void cp_async16(uint32_t dst, const void* src) {
    asm volatile("cp.async.cg.shared.global [%0], [%1], 16;" :: "r"(dst), "l"(src));
}
__device__ __forceinline__ void ldmatrix_x4(uint32_t* r, uint32_t addr) {
    asm volatile("ldmatrix.sync.aligned.m8n8.x4.shared.b16 {%0,%1,%2,%3}, [%4];"
                 : "=r"(r[0]), "=r"(r[1]), "=r"(r[2]), "=r"(r[3]) : "r"(addr));
}
__device__ __forceinline__ void mma16816(float* c, const uint32_t* a,
                                         uint32_t b0, uint32_t b1) {
    asm volatile(
        "mma.sync.aligned.m16n8k16.row.col.f32.f16.f16.f32 "
        "{%0,%1,%2,%3}, {%4,%5,%6,%7}, {%8,%9}, {%0,%1,%2,%3};"
        : "+f"(c[0]), "+f"(c[1]), "+f"(c[2]), "+f"(c[3])
        : "r"(a[0]), "r"(a[1]), "r"(a[2]), "r"(a[3]), "r"(b0), "r"(b1));
}
__device__ __forceinline__ __half2 u2h(uint32_t u) {
    return *reinterpret_cast<__half2*>(&u);
}
__device__ __forceinline__ float sig_fast(float x) {
    float r;
    asm("rcp.approx.f32 %0, %1;" : "=f"(r) : "f"(1.f + __expf(-x)));
    return r;
}
__device__ __forceinline__ float tanh_fast(float x) {
    float r;
    asm("rcp.approx.f32 %0, %1;" : "=f"(r) : "f"(1.f + __expf(-2.f * x)));
    return fmaf(2.f, r, -1.f);
}

// ============================================================================
// Kernel 0: fp32 -> fp16 conversion (x and W_ih)
// ============================================================================
__global__ void __launch_bounds__(256)
f2h_kernel(const float* __restrict__ src, __half* __restrict__ dst, int n)
{
    int i = (blockIdx.x * 256 + threadIdx.x) * 8;
    if (i >= n) return;
    const float4 a = *(const float4*)(src + i);
    const float4 b = *(const float4*)(src + i + 4);
    __half2 h0 = __floats2half2_rn(a.x, a.y);
    __half2 h1 = __floats2half2_rn(a.z, a.w);
    __half2 h2 = __floats2half2_rn(b.x, b.y);
    __half2 h3 = __floats2half2_rn(b.z, b.w);
    uint4 o;
    o.x = *(uint32_t*)&h0; o.y = *(uint32_t*)&h1;
    o.z = *(uint32_t*)&h2; o.w = *(uint32_t*)&h3;
    *(uint4*)(dst + i) = o;
}

// ============================================================================
// Kernel 1: xg = x @ W_ih^T + b_ih + b_hh  via mma.sync.m16n8k16 (fp16->fp32).
// 128x128 tile / CTA, 8 warps of 64x32, 4-stage cp.async pipeline over K.
// ============================================================================
__global__ void __launch_bounds__(256, 1)
gemm_xg_mma(const float* __restrict__ b1, const float* __restrict__ b2)
{
    extern __shared__ char dynsmem[];
    __shared__ float s_bias[BN];

    const int tid    = threadIdx.x;
    const int lane   = tid & 31;
    const int wid    = tid >> 5;
    const int warp_m = wid >> 2;            // 0..1
    const int warp_n = wid & 3;             // 0..3
    const int mw     = warp_m * 64;
    const int nb     = warp_n * 32;
    const int n0     = blockIdx.x * BN;
    const int m0     = blockIdx.y * BM;

    const uint32_t sm0 = smem_u32(dynsmem);

    if (tid < BN) s_bias[tid] = b1[n0 + tid] + b2[n0 + tid];

    const __half* gA = g_xh + (size_t)m0 * IDIM;
    const __half* gB = g_wh + (size_t)n0 * IDIM;

    auto load_chunk = [&](int kc) {
        const uint32_t base = sm0 + (uint32_t)(kc & (STAGES - 1)) * STG_B;
        const int k0 = kc * BK;
#pragma unroll
        for (int part = 0; part < 4; ++part) {
            const int idx = part * 256 + tid;           // 0..1023
            const int row = (idx >> 2) & 127;
            const int seg = idx & 3;
            const uint32_t doff = (uint32_t)(row * (APAD * 2) + seg * 16);
            if (idx < 512)
                cp_async16(base + doff, gA + (size_t)row * IDIM + k0 + seg * 8);
            else
                cp_async16(base + STG_A + doff, gB + (size_t)row * IDIM + k0 + seg * 8);
        }
        asm volatile("cp.async.commit_group;" ::: "memory");
    };

    float acc[4][4][4];
#pragma unroll
    for (int mi = 0; mi < 4; ++mi)
#pragma unroll
        for (int ni = 0; ni < 4; ++ni)
#pragma unroll
            for (int q = 0; q < 4; ++q) acc[mi][ni][q] = 0.f;

    load_chunk(0);
    load_chunk(1);
    load_chunk(2);

    for (int kc = 0; kc < NCH; ++kc) {
        const int pf = kc + STAGES - 1;
        if (pf < NCH) load_chunk(pf);

        if (kc <= NCH - STAGES)
            asm volatile("cp.async.wait_group %0;" :: "n"(STAGES - 1) : "memory");
        else if (kc == NCH - 3)
            asm volatile("cp.async.wait_group 2;" ::: "memory");
        else if (kc == NCH - 2)
            asm volatile("cp.async.wait_group 1;" ::: "memory");
        else
            asm volatile("cp.async.wait_group 0;" ::: "memory");
        __syncthreads();

        const uint32_t as_ = sm0 + (uint32_t)(kc & (STAGES - 1)) * STG_B;
        const uint32_t bs_ = as_ + STG_A;

#pragma unroll
        for (int s = 0; s < 2; ++s) {               // two k16 steps
            uint32_t af[4][4];
#pragma unroll
            for (int mi = 0; mi < 4; ++mi) {
                const uint32_t addr = as_
                    + (uint32_t)(mw + mi * 16 + (lane & 15)) * (APAD * 2)
                    + (uint32_t)(s * 16 + ((lane >> 4) << 3)) * 2;
                ldmatrix_x4(af[mi], addr);
            }
            uint32_t bf[2][4];
#pragma unroll
            for (int g = 0; g < 2; ++g) {
                const uint32_t addr = bs_
                    + (uint32_t)(nb + g * 16 + (lane & 7) + (((lane >> 4) & 1) << 3)) * (APAD * 2)
                    + (uint32_t)(s * 16 + (((lane >> 3) & 1) << 3)) * 2;
                ldmatrix_x4(bf[g], addr);
            }
#pragma unroll
            for (int mi = 0; mi < 4; ++mi)
#pragma unroll
                for (int ni = 0; ni < 4; ++ni)
                    mma16816(acc[mi][ni], af[mi],
                             bf[ni >> 1][(ni & 1) * 2],
                             bf[ni >> 1][(ni & 1) * 2 + 1]);
        }
        __syncthreads();
    }

#pragma unroll
    for (int mi = 0; mi < 4; ++mi) {
        const int r0 = m0 + mw + mi * 16 + (lane >> 2);
#pragma unroll
        for (int ni = 0; ni < 4; ++ni) {
            const int c = nb + ni * 8 + (lane & 3) * 2;
            const float bb0 = s_bias[c];
            const float bb1 = s_bias[c + 1];
            float2 v0, v1;
            v0.x = acc[mi][ni][0] + bb0; v0.y = acc[mi][ni][1] + bb1;
            v1.x = acc[mi][ni][2] + bb0; v1.y = acc[mi][ni][3] + bb1;
            *(float2*)&g_xg[(size_t)r0 * GROWS + n0 + c]       = v0;
            *(float2*)&g_xg[(size_t)(r0 + 8) * GROWS + n0 + c] = v1;
        }
    }
}

// ============================================================================
// Kernel 2: persistent LSTM recurrence, 32 warps = 4 k-groups x 8 row-groups.
// Release/acquire flag barrier (no membar/IVALL, REDG arrival), __stcg h
// stores, __ldcv h loads, HFMA2 inner product, fast activations.
// ============================================================================
__global__ void __launch_bounds__(RTHREADS, 1)
lstm_persistent(const float* __restrict__ W_hh)
{
    extern __shared__ __half sw[];
    __shared__ float4 s_part[MAXROWS];    // [row] -> 4 kgrp partials
    __shared__ float  s_c[UPC];

    const int tid   = threadIdx.x;
    const int wid   = tid >> 5;
    const int lane  = tid & 31;
    const int kgrp  = wid >> 3;           // 0..3
    const int rgrp  = wid & 7;            // 0..7
    const int cta   = blockIdx.x;
    const int u0    = cta * UPC;
    const int nu    = (HDIM - u0 < UPC) ? (HDIM - u0) : UPC;
    const int nrows = 4 * nu;
    const int koff  = kgrp * 512 + lane * 8;   // halves

    // one-time: W_hh rows -> SMEM fp16
    for (int e = tid * 4; e < nrows * HDIM; e += RTHREADS * 4) {
        int r    = e / HDIM;
        int k    = e - r * HDIM;
        int gate = r / nu;
        int u    = r - gate * nu;
        const float4 v = *(const float4*)&W_hh[(size_t)(gate * HDIM + u0 + u) * HDIM + k];
        __half2* dst = (__half2*)&sw[r * HDIM + k];
        dst[0] = __floats2half2_rn(v.x, v.y);
        dst[1] = __floats2half2_rn(v.z, v.w);
    }
    if (tid < UPC)     s_c[tid]    = 0.f;
    if (tid < MAXROWS) s_part[tid] = make_float4(0.f, 0.f, 0.f, 0.f);

    unsigned base = 0u;
    if (tid == 0) base = *(volatile unsigned*)&g_base;
    __syncthreads();

    for (int t = 0; t < SEQ; ++t) {
        // prefetch xg (independent of h; xg is never stale -> plain LDG fine)
        float xgv0 = 0.f, xgv1 = 0.f, xgv2 = 0.f, xgv3 = 0.f;
        if (tid < nu) {
            const float* xp = g_xg + (size_t)t * GROWS + u0 + tid;
            xgv0 = xp[0 * HDIM];
            xgv1 = xp[1 * HDIM];
            xgv2 = xp[2 * HDIM];
            xgv3 = xp[3 * HDIM];
        }

        if (t > 0) {
            __syncthreads();   // (A) step t-1 h stores issued CTA-wide
            if (tid == 0) {
                const unsigned tgt = base + (unsigned)NCTA * (unsigned)t;
                // release arrival: orders our CTA's h stores (st.cg, already
                // at L2) before the counter increment; no membar, no IVALL
                asm volatile("red.release.gpu.global.add.u32 [%0], %1;"
                             :: "l"(&g_bar), "r"(1u) : "memory");
                unsigned v;
                do {
                    asm volatile("ld.acquire.gpu.global.u32 %0, [%1];"
                                 : "=r"(v) : "l"(&g_bar) : "memory");
                } while ((int)(v - tgt) < 0);
            }
            __syncthreads();   // (B)

            // h slice for this warp's k-range: 16 floats via L2-direct loads,
            // converted once per step to 8 half2 for the HFMA2 inner loop
            const float* hb = g_h[t & 1];
            const float4 h0 = __ldcv((const float4*)&hb[koff]);
            const float4 h1 = __ldcv((const float4*)&hb[koff + 4]);
            const float4 h2 = __ldcv((const float4*)&hb[koff + 256]);
            const float4 h3 = __ldcv((const float4*)&hb[koff + 260]);
            __half2 hh[8];
            hh[0] = __floats2half2_rn(h0.x, h0.y);
            hh[1] = __floats2half2_rn(h0.z, h0.w);
            hh[2] = __floats2half2_rn(h1.x, h1.y);
            hh[3] = __floats2half2_rn(h1.z, h1.w);
            hh[4] = __floats2half2_rn(h2.x, h2.y);
            hh[5] = __floats2half2_rn(h2.z, h2.w);
            hh[6] = __floats2half2_rn(h3.x, h3.y);
            hh[7] = __floats2half2_rn(h3.z, h3.w);

            for (int r = rgrp; r < nrows; r += 8) {
                const __half* wr = sw + r * HDIM + koff;
                const uint4 wv0 = *(const uint4*)(wr);
                const uint4 wv1 = *(const uint4*)(wr + 256);
                __half2 a0 = __hmul2(u2h(wv0.x), hh[0]);
                a0 = __hfma2(u2h(wv0.y), hh[1], a0);
                __half2 a1 = __hmul2(u2h(wv0.z), hh[2]);
                a1 = __hfma2(u2h(wv0.w), hh[3], a1);
                __half2 a2 = __hmul2(u2h(wv1.x), hh[4]);
                a2 = __hfma2(u2h(wv1.y), hh[5], a2);
                __half2 a3 = __hmul2(u2h(wv1.z), hh[6]);
                a3 = __hfma2(u2h(wv1.w), hh[7], a3);
                const float2 f0 = __half22float2(a0);
                const float2 f1 = __half22float2(a1);
                const float2 f2 = __half22float2(a2);
                const float2 f3 = __half22float2(a3);
                float acc = ((f0.x + f0.y) + (f1.x + f1.y))
                          + ((f2.x + f2.y) + (f3.x + f3.y));
#pragma unroll
                for (int off = 16; off; off >>= 1)
                    acc += __shfl_xor_sync(0xffffffffu, acc, off);
                if (lane == 0) ((float*)&s_part[r])[kgrp] = acc;
            }
        }
        __syncthreads();       // (C) s_part complete

        if (tid < nu) {
            const float4 pi = s_part[0 * nu + tid];
            const float4 pf = s_part[1 * nu + tid];
            const float4 pg = s_part[2 * nu + tid];
            const float4 po = s_part[3 * nu + tid];
            const float gi = xgv0 + (pi.x + pi.y) + (pi.z + pi.w);
            const float gf = xgv1 + (pf.x + pf.y) + (pf.z + pf.w);
            const float gg = xgv2 + (pg.x + pg.y) + (pg.z + pg.w);
            const float go = xgv3 + (po.x + po.y) + (po.z + po.w);
            const float ig = sig_fast(gi);
            const float fg = sig_fast(gf);
            const float g2 = tanh_fast(gg);
            const float og = sig_fast(go);
            const float cc = fg * s_c[tid] + ig * g2;
            s_c[tid] = cc;
            __stcg(&g_h[(t + 1) & 1][u0 + tid], og * tanh_fast(cc));
        }
    }

    // final barrier: safe epoch-base update for the next graph replay
    __syncthreads();
    if (tid == 0) {
        __threadfence();
        atomicAdd(&g_bar, 1u);
        unsigned tgt = base + (unsigned)NCTA * (unsigned)SEQ;
        while ((int)(*(volatile unsigned*)&g_bar - tgt) < 0) { }
        if (cta == 0) *(volatile unsigned*)&g_base = tgt;
    }
}

// ============================================================================
// Kernel 3: out = h_last @ W_fc^T + b_fc   (h_last in g_h[0]; SEQ even)
// ============================================================================
__global__ void __launch_bounds__(256)
fc_kernel(const float* __restrict__ Wfc, const float* __restrict__ bfc,
          float* __restrict__ out)
{
    const int o    = blockIdx.x * 8 + (threadIdx.x >> 5);
    const int lane = threadIdx.x & 31;
    const float* hb = g_h[0];
    const float* wr = Wfc + (size_t)o * HDIM;
    float acc = 0.f;
#pragma unroll
    for (int i = 0; i < 16; ++i) {
        const int k = i * 128 + lane * 4;
        const float4 w  = *(const float4*)&wr[k];
        const float4 h4 = *(const float4*)&hb[k];
        acc += w.x * h4.x + w.y * h4.y + w.z * h4.z + w.w * h4.w;
    }
#pragma unroll
    for (int off = 16; off; off >>= 1)
        acc += __shfl_xor_sync(0xffffffffu, acc, off);
    if (lane == 0) out[o] = acc + bfc[o];
}

// ============================================================================
extern "C" void kernel_launch(void* const* d_in, const int* in_sizes, int n_in,
                              void* d_out, int out_size)
{
    const float* x   = (const float*)d_in[0];
    const float* Wih = (const float*)d_in[1];
    const float* Whh = (const float*)d_in[2];
    const float* bih = (const float*)d_in[3];
    const float* bhh = (const float*)d_in[4];
    const float* Wfc = (const float*)d_in[5];
    const float* bfc = (const float*)d_in[6];
    float* out = (float*)d_out;

    static __half* p_xh = nullptr;
    static __half* p_wh = nullptr;
    if (!p_xh) {
        cudaGetSymbolAddress((void**)&p_xh, g_xh);
        cudaGetSymbolAddress((void**)&p_wh, g_wh);
        cudaFuncSetAttribute(gemm_xg_mma,
                             cudaFuncAttributeMaxDynamicSharedMemorySize,
                             (int)GEMM_SMEM);
        cudaFuncSetAttribute(lstm_persistent,
                             cudaFuncAttributeMaxDynamicSharedMemorySize,
                             (int)SW_BYTES);
    }

    f2h_kernel<<<(SEQ * IDIM / 8 + 255) / 256, 256>>>(x, p_xh, SEQ * IDIM);
    f2h_kernel<<<(GROWS * IDIM / 8 + 255) / 256, 256>>>(Wih, p_wh, GROWS * IDIM);
    gemm_xg_mma<<<dim3(GROWS / BN, SEQ / BM), 256, GEMM_SMEM>>>(bih, bhh);
    lstm_persistent<<<NCTA, RTHREADS, SW_BYTES>>>(Whh);
    fc_kernel<<<OUTD / 8, 256>>>(Wfc, bfc, out);
}

// round 11
// speedup vs baseline: 1.5288x; 1.5288x over previous
#include <cuda_runtime.h>
#include <cuda_fp16.h>
#include <math.h>
#include <stdint.h>

// Problem dims
#define SEQ    4096
#define IDIM   2048
#define HDIM   2048
#define GROWS  8192   // 4*HDIM, PyTorch gate order i,f,g,o
#define OUTD   2048

// Persistent recurrence kernel config
#define UPC      14
#define NCTA     147
#define RTHREADS 1024             // 32 warps: 4 k-groups x 8 row-groups
#define MAXROWS  (4*UPC)
#define SW_BYTES (MAXROWS*HDIM*sizeof(__half))   // 229376 B

// mma.sync GEMM config
#define BM 128
#define BN 128
#define BK 32
#define NCH    (IDIM/BK)          // 64 k-chunks
#define STAGES 4
#define APAD   40                 // halves per SMEM row (32 + 8 pad) -> 80B stride
#define STG_A  (BM*APAD*2)        // 10240 B
#define STG_B  (2*STG_A)          // 20480 B per stage (A then B)
#define GEMM_SMEM (STAGES*STG_B)  // 81920 B

// -------- device scratch (static allocation only) --------
__device__ float    g_xg[(size_t)SEQ * GROWS];   // 128 MB
__device__ __half   g_xh[(size_t)SEQ * IDIM];    // 16 MB  x in fp16
__device__ __half   g_wh[(size_t)GROWS * IDIM];  // 32 MB  W_ih in fp16
__device__ float    g_h[2][HDIM];
__device__ unsigned g_bar  = 0u;                 // monotonic arrival counter
__device__ unsigned g_base = 0u;                 // epoch base across graph replays

// ---------------- PTX helpers (all sm_80+; no arch-suffix features) ----------
__device__ __forceinline__ uint32_t smem_u32(const void* p) {
    return (uint32_t)__cvta_generic_to_shared(p);
}
__device__ __forceinline__ void cp_async16(uint32_t dst, const void* src) {
    asm volatile("cp.async.cg.shared.global [%0], [%1], 16;" :: "r"(dst), "l"(src));
}
__device__ __forceinline__ void ldmatrix_x4(uint32_t* r, uint32_t addr) {
    asm volatile("ldmatrix.sync.aligned.m8n8.x4.shared.b16 {%0,%1,%2,%3}, [%4];"
                 : "=r"(r[0]), "=r"(r[1]), "=r"(r[2]), "=r"(r[3]) : "r"(addr));
}
__device__ __forceinline__ void mma16816(float* c, const uint32_t* a,
                                         uint32_t b0, uint32_t b1) {
    asm volatile(
        "mma.sync.aligned.m16n8k16.row.col.f32.f16.f16.f32 "
        "{%0,%1,%2,%3}, {%4,%5,%6,%7}, {%8,%9}, {%0,%1,%2,%3};"
        : "+f"(c[0]), "+f"(c[1]), "+f"(c[2]), "+f"(c[3])
        : "r"(a[0]), "r"(a[1]), "r"(a[2]), "r"(a[3]), "r"(b0), "r"(b1));
}
__device__ __forceinline__ __half2 u2h(uint32_t u) {
    return *reinterpret_cast<__half2*>(&u);
}
__device__ __forceinline__ float sig_fast(float x) {
    float r;
    asm("rcp.approx.f32 %0, %1;" : "=f"(r) : "f"(1.f + __expf(-x)));
    return r;
}
__device__ __forceinline__ float tanh_fast(float x) {
    float r;
    asm("rcp.approx.f32 %0, %1;" : "=f"(r) : "f"(1.f + __expf(-2.f * x)));
    return fmaf(2.f, r, -1.f);
}

// ============================================================================
// Kernel 0: fp32 -> fp16 conversion (x and W_ih)
// ============================================================================
__global__ void __launch_bounds__(256)
f2h_kernel(const float* __restrict__ src, __half* __restrict__ dst, int n)
{
    int i = (blockIdx.x * 256 + threadIdx.x) * 8;
    if (i >= n) return;
    const float4 a = *(const float4*)(src + i);
    const float4 b = *(const float4*)(src + i + 4);
    __half2 h0 = __floats2half2_rn(a.x, a.y);
    __half2 h1 = __floats2half2_rn(a.z, a.w);
    __half2 h2 = __floats2half2_rn(b.x, b.y);
    __half2 h3 = __floats2half2_rn(b.z, b.w);
    uint4 o;
    o.x = *(uint32_t*)&h0; o.y = *(uint32_t*)&h1;
    o.z = *(uint32_t*)&h2; o.w = *(uint32_t*)&h3;
    *(uint4*)(dst + i) = o;
}

// ============================================================================
// Kernel 1: xg = x @ W_ih^T + b_ih + b_hh  via mma.sync.m16n8k16 (fp16->fp32).
// 128x128 tile / CTA, 8 warps of 64x32, 4-stage cp.async pipeline over K.
// ============================================================================
__global__ void __launch_bounds__(256, 1)
gemm_xg_mma(const float* __restrict__ b1, const float* __restrict__ b2)
{
    extern __shared__ char dynsmem[];
    __shared__ float s_bias[BN];

    const int tid    = threadIdx.x;
    const int lane   = tid & 31;
    const int wid    = tid >> 5;
    const int warp_m = wid >> 2;            // 0..1
    const int warp_n = wid & 3;             // 0..3
    const int mw     = warp_m * 64;
    const int nb     = warp_n * 32;
    const int n0     = blockIdx.x * BN;
    const int m0     = blockIdx.y * BM;

    const uint32_t sm0 = smem_u32(dynsmem);

    if (tid < BN) s_bias[tid] = b1[n0 + tid] + b2[n0 + tid];

    const __half* gA = g_xh + (size_t)m0 * IDIM;
    const __half* gB = g_wh + (size_t)n0 * IDIM;

    auto load_chunk = [&](int kc) {
        const uint32_t base = sm0 + (uint32_t)(kc & (STAGES - 1)) * STG_B;
        const int k0 = kc * BK;
#pragma unroll
        for (int part = 0; part < 4; ++part) {
            const int idx = part * 256 + tid;           // 0..1023
            const int row = (idx >> 2) & 127;
            const int seg = idx & 3;
            const uint32_t doff = (uint32_t)(row * (APAD * 2) + seg * 16);
            if (idx < 512)
                cp_async16(base + doff, gA + (size_t)row * IDIM + k0 + seg * 8);
            else
                cp_async16(base + STG_A + doff, gB + (size_t)row * IDIM + k0 + seg * 8);
        }
        asm volatile("cp.async.commit_group;" ::: "memory");
    };

    float acc[4][4][4];
#pragma unroll
    for (int mi = 0; mi < 4; ++mi)
#pragma unroll
        for (int ni = 0; ni < 4; ++ni)
#pragma unroll
            for (int q = 0; q < 4; ++q) acc[mi][ni][q] = 0.f;

    load_chunk(0);
    load_chunk(1);
    load_chunk(2);

    for (int kc = 0; kc < NCH; ++kc) {
        const int pf = kc + STAGES - 1;
        if (pf < NCH) load_chunk(pf);

        if (kc <= NCH - STAGES)
            asm volatile("cp.async.wait_group %0;" :: "n"(STAGES - 1) : "memory");
        else if (kc == NCH - 3)
            asm volatile("cp.async.wait_group 2;" ::: "memory");
        else if (kc == NCH - 2)
            asm volatile("cp.async.wait_group 1;" ::: "memory");
        else
            asm volatile("cp.async.wait_group 0;" ::: "memory");
        __syncthreads();

        const uint32_t as_ = sm0 + (uint32_t)(kc & (STAGES - 1)) * STG_B;
        const uint32_t bs_ = as_ + STG_A;

#pragma unroll
        for (int s = 0; s < 2; ++s) {               // two k16 steps
            uint32_t af[4][4];
#pragma unroll
            for (int mi = 0; mi < 4; ++mi) {
                const uint32_t addr = as_
                    + (uint32_t)(mw + mi * 16 + (lane & 15)) * (APAD * 2)
                    + (uint32_t)(s * 16 + ((lane >> 4) << 3)) * 2;
                ldmatrix_x4(af[mi], addr);
            }
            uint32_t bf[2][4];
#pragma unroll
            for (int g = 0; g < 2; ++g) {
                const uint32_t addr = bs_
                    + (uint32_t)(nb + g * 16 + (lane & 7) + (((lane >> 4) & 1) << 3)) * (APAD * 2)
                    + (uint32_t)(s * 16 + (((lane >> 3) & 1) << 3)) * 2;
                ldmatrix_x4(bf[g], addr);
            }
#pragma unroll
            for (int mi = 0; mi < 4; ++mi)
#pragma unroll
                for (int ni = 0; ni < 4; ++ni)
                    mma16816(acc[mi][ni], af[mi],
                             bf[ni >> 1][(ni & 1) * 2],
                             bf[ni >> 1][(ni & 1) * 2 + 1]);
        }
        __syncthreads();
    }

#pragma unroll
    for (int mi = 0; mi < 4; ++mi) {
        const int r0 = m0 + mw + mi * 16 + (lane >> 2);
#pragma unroll
        for (int ni = 0; ni < 4; ++ni) {
            const int c = nb + ni * 8 + (lane & 3) * 2;
            const float bb0 = s_bias[c];
            const float bb1 = s_bias[c + 1];
            float2 v0, v1;
            v0.x = acc[mi][ni][0] + bb0; v0.y = acc[mi][ni][1] + bb1;
            v1.x = acc[mi][ni][2] + bb0; v1.y = acc[mi][ni][3] + bb1;
            *(float2*)&g_xg[(size_t)r0 * GROWS + n0 + c]       = v0;
            *(float2*)&g_xg[(size_t)(r0 + 8) * GROWS + n0 + c] = v1;
        }
    }
}

// ============================================================================
// Kernel 2: persistent LSTM recurrence, 32 warps = 4 k-groups x 8 row-groups.
// Round-9 proven skeleton (threadfence + central atomic barrier, plain LDG h
// loads shared via L1, plain stores) with HFMA2 inner product and fast
// activations as the only changes.
// ============================================================================
__global__ void __launch_bounds__(RTHREADS, 1)
lstm_persistent(const float* __restrict__ W_hh)
{
    extern __shared__ __half sw[];
    __shared__ float4 s_part[MAXROWS];    // [row] -> 4 kgrp partials
    __shared__ float  s_c[UPC];

    const int tid   = threadIdx.x;
    const int wid   = tid >> 5;
    const int lane  = tid & 31;
    const int kgrp  = wid >> 3;           // 0..3
    const int rgrp  = wid & 7;            // 0..7
    const int cta   = blockIdx.x;
    const int u0    = cta * UPC;
    const int nu    = (HDIM - u0 < UPC) ? (HDIM - u0) : UPC;
    const int nrows = 4 * nu;
    const int koff  = kgrp * 512 + lane * 8;   // halves

    // one-time: W_hh rows -> SMEM fp16
    for (int e = tid * 4; e < nrows * HDIM; e += RTHREADS * 4) {
        int r    = e / HDIM;
        int k    = e - r * HDIM;
        int gate = r / nu;
        int u    = r - gate * nu;
        const float4 v = *(const float4*)&W_hh[(size_t)(gate * HDIM + u0 + u) * HDIM + k];
        __half2* dst = (__half2*)&sw[r * HDIM + k];
        dst[0] = __floats2half2_rn(v.x, v.y);
        dst[1] = __floats2half2_rn(v.z, v.w);
    }
    if (tid < UPC)     s_c[tid]    = 0.f;
    if (tid < MAXROWS) s_part[tid] = make_float4(0.f, 0.f, 0.f, 0.f);

    unsigned base = 0u;
    if (tid == 0) base = *(volatile unsigned*)&g_base;
    __syncthreads();

    for (int t = 0; t < SEQ; ++t) {
        // prefetch xg (independent of h)
        float xgv0 = 0.f, xgv1 = 0.f, xgv2 = 0.f, xgv3 = 0.f;
        if (tid < nu) {
            const float* xp = g_xg + (size_t)t * GROWS + u0 + tid;
            xgv0 = xp[0 * HDIM];
            xgv1 = xp[1 * HDIM];
            xgv2 = xp[2 * HDIM];
            xgv3 = xp[3 * HDIM];
        }

        if (t > 0) {
            __syncthreads();   // (A) step t-1 complete CTA-wide
            if (tid == 0) {
                __threadfence();                       // release our h slice
                atomicAdd(&g_bar, 1u);
                unsigned tgt = base + (unsigned)NCTA * (unsigned)t;
                while ((int)(*(volatile unsigned*)&g_bar - tgt) < 0) { }
                __threadfence();                       // acquire + fresh L1
            }
            __syncthreads();   // (B)

            // h slice for this warp's k-range: 16 floats (L1-shared across
            // the CTA's warps after the single IVALL), converted once to half2
            const float* hb = g_h[t & 1];
            const float4 h0 = *(const float4*)&hb[koff];
            const float4 h1 = *(const float4*)&hb[koff + 4];
            const float4 h2 = *(const float4*)&hb[koff + 256];
            const float4 h3 = *(const float4*)&hb[koff + 260];
            __half2 hh[8];
            hh[0] = __floats2half2_rn(h0.x, h0.y);
            hh[1] = __floats2half2_rn(h0.z, h0.w);
            hh[2] = __floats2half2_rn(h1.x, h1.y);
            hh[3] = __floats2half2_rn(h1.z, h1.w);
            hh[4] = __floats2half2_rn(h2.x, h2.y);
            hh[5] = __floats2half2_rn(h2.z, h2.w);
            hh[6] = __floats2half2_rn(h3.x, h3.y);
            hh[7] = __floats2half2_rn(h3.z, h3.w);

            for (int r = rgrp; r < nrows; r += 8) {
                const __half* wr = sw + r * HDIM + koff;
                const uint4 wv0 = *(const uint4*)(wr);
                const uint4 wv1 = *(const uint4*)(wr + 256);
                __half2 a0 = __hmul2(u2h(wv0.x), hh[0]);
                a0 = __hfma2(u2h(wv0.y), hh[1], a0);
                __half2 a1 = __hmul2(u2h(wv0.z), hh[2]);
                a1 = __hfma2(u2h(wv0.w), hh[3], a1);
                __half2 a2 = __hmul2(u2h(wv1.x), hh[4]);
                a2 = __hfma2(u2h(wv1.y), hh[5], a2);
                __half2 a3 = __hmul2(u2h(wv1.z), hh[6]);
                a3 = __hfma2(u2h(wv1.w), hh[7], a3);
                const float2 f0 = __half22float2(a0);
                const float2 f1 = __half22float2(a1);
                const float2 f2 = __half22float2(a2);
                const float2 f3 = __half22float2(a3);
                float acc = ((f0.x + f0.y) + (f1.x + f1.y))
                          + ((f2.x + f2.y) + (f3.x + f3.y));
#pragma unroll
                for (int off = 16; off; off >>= 1)
                    acc += __shfl_xor_sync(0xffffffffu, acc, off);
                if (lane == 0) ((float*)&s_part[r])[kgrp] = acc;
            }
        }
        __syncthreads();       // (C) s_part complete

        if (tid < nu) {
            const float4 pi = s_part[0 * nu + tid];
            const float4 pf = s_part[1 * nu + tid];
            const float4 pg = s_part[2 * nu + tid];
            const float4 po = s_part[3 * nu + tid];
            const float gi = xgv0 + (pi.x + pi.y) + (pi.z + pi.w);
            const float gf = xgv1 + (pf.x + pf.y) + (pf.z + pf.w);
            const float gg = xgv2 + (pg.x + pg.y) + (pg.z + pg.w);
            const float go = xgv3 + (po.x + po.y) + (po.z + po.w);
            const float ig = sig_fast(gi);
            const float fg = sig_fast(gf);
            const float g2 = tanh_fast(gg);
            const float og = sig_fast(go);
            const float cc = fg * s_c[tid] + ig * g2;
            s_c[tid] = cc;
            g_h[(t + 1) & 1][u0 + tid] = og * tanh_fast(cc);
        }
    }

    // final barrier: safe epoch-base update for the next graph replay
    __syncthreads();
    if (tid == 0) {
        __threadfence();
        atomicAdd(&g_bar, 1u);
        unsigned tgt = base + (unsigned)NCTA * (unsigned)SEQ;
        while ((int)(*(volatile unsigned*)&g_bar - tgt) < 0) { }
        if (cta == 0) *(volatile unsigned*)&g_base = tgt;
    }
}

// ============================================================================
// Kernel 3: out = h_last @ W_fc^T + b_fc   (h_last in g_h[0]; SEQ even)
// ============================================================================
__global__ void __launch_bounds__(256)
fc_kernel(const float* __restrict__ Wfc, const float* __restrict__ bfc,
          float* __restrict__ out)
{
    const int o    = blockIdx.x * 8 + (threadIdx.x >> 5);
    const int lane = threadIdx.x & 31;
    const float* hb = g_h[0];
    const float* wr = Wfc + (size_t)o * HDIM;
    float acc = 0.f;
#pragma unroll
    for (int i = 0; i < 16; ++i) {
        const int k = i * 128 + lane * 4;
        const float4 w  = *(const float4*)&wr[k];
        const float4 h4 = *(const float4*)&hb[k];
        acc += w.x * h4.x + w.y * h4.y + w.z * h4.z + w.w * h4.w;
    }
#pragma unroll
    for (int off = 16; off; off >>= 1)
        acc += __shfl_xor_sync(0xffffffffu, acc, off);
    if (lane == 0) out[o] = acc + bfc[o];
}

// ============================================================================
extern "C" void kernel_launch(void* const* d_in, const int* in_sizes, int n_in,
                              void* d_out, int out_size)
{
    const float* x   = (const float*)d_in[0];
    const float* Wih = (const float*)d_in[1];
    const float* Whh = (const float*)d_in[2];
    const float* bih = (const float*)d_in[3];
    const float* bhh = (const float*)d_in[4];
    const float* Wfc = (const float*)d_in[5];
    const float* bfc = (const float*)d_in[6];
    float* out = (float*)d_out;

    static __half* p_xh = nullptr;
    static __half* p_wh = nullptr;
    if (!p_xh) {
        cudaGetSymbolAddress((void**)&p_xh, g_xh);
        cudaGetSymbolAddress((void**)&p_wh, g_wh);
        cudaFuncSetAttribute(gemm_xg_mma,
                             cudaFuncAttributeMaxDynamicSharedMemorySize,
                             (int)GEMM_SMEM);
        cudaFuncSetAttribute(lstm_persistent,
                             cudaFuncAttributeMaxDynamicSharedMemorySize,
                             (int)SW_BYTES);
    }

    f2h_kernel<<<(SEQ * IDIM / 8 + 255) / 256, 256>>>(x, p_xh, SEQ * IDIM);
    f2h_kernel<<<(GROWS * IDIM / 8 + 255) / 256, 256>>>(Wih, p_wh, GROWS * IDIM);
    gemm_xg_mma<<<dim3(GROWS / BN, SEQ / BM), 256, GEMM_SMEM>>>(bih, bhh);
    lstm_persistent<<<NCTA, RTHREADS, SW_BYTES>>>(Whh);
    fc_kernel<<<OUTD / 8, 256>>>(Wfc, bfc, out);
}

// round 14
// speedup vs baseline: 1.7129x; 1.1204x over previous
#include <cuda_runtime.h>
#include <cuda_fp16.h>
#include <math.h>
#include <stdint.h>

// Problem dims
#define SEQ    4096
#define IDIM   2048
#define HDIM   2048
#define GROWS  8192   // 4*HDIM, PyTorch gate order i,f,g,o
#define OUTD   2048

// Persistent recurrence kernel config
#define UPC      14
#define NCTA     147
#define RTHREADS 1024             // 32 warps: 4 k-groups x 8 row-groups
#define MAXROWS  (4*UPC)
#define SW_BYTES (MAXROWS*HDIM*sizeof(__half))   // 229376 B

// mma.sync GEMM config
#define BM 128
#define BN 128
#define BK 32
#define NCH    (IDIM/BK)          // 64 k-chunks
#define STAGES 4
#define APAD   40                 // halves per SMEM row (32 + 8 pad) -> 80B stride
#define STG_A  (BM*APAD*2)        // 10240 B
#define STG_B  (2*STG_A)          // 20480 B per stage (A then B)
#define GEMM_SMEM (STAGES*STG_B)  // 81920 B

// -------- device scratch (static allocation only) --------
__device__ float    g_xg[(size_t)SEQ * GROWS];   // 128 MB
__device__ __half   g_xh[(size_t)SEQ * IDIM];    // 16 MB  x in fp16
__device__ __half   g_wh[(size_t)GROWS * IDIM];  // 32 MB  W_ih in fp16
__device__ float    g_h[2][HDIM];                // fp32 h (final FC reads this)
__device__ __half   g_hh[2][HDIM];               // fp16 h broadcast copy
__device__ unsigned g_bar  = 0u;                 // monotonic arrival counter
__device__ unsigned g_base = 0u;                 // epoch base across graph replays

// ---------------- PTX helpers (all sm_80+; no arch-suffix features) ----------
__device__ __forceinline__ uint32_t smem_u32(const void* p) {
    return (uint32_t)__cvta_generic_to_shared(p);
}
__device__ __forceinline__ void cp_async16(uint32_t dst, const void* src) {
    asm volatile("cp.async.cg.shared.global [%0], [%1], 16;" :: "r"(dst), "l"(src));
}
__device__ __forceinline__ void ldmatrix_x4(uint32_t* r, uint32_t addr) {
    asm volatile("ldmatrix.sync.aligned.m8n8.x4.shared.b16 {%0,%1,%2,%3}, [%4];"
                 : "=r"(r[0]), "=r"(r[1]), "=r"(r[2]), "=r"(r[3]) : "r"(addr));
}
__device__ __forceinline__ void mma16816(float* c, const uint32_t* a,
                                         uint32_t b0, uint32_t b1) {
    asm volatile(
        "mma.sync.aligned.m16n8k16.row.col.f32.f16.f16.f32 "
        "{%0,%1,%2,%3}, {%4,%5,%6,%7}, {%8,%9}, {%0,%1,%2,%3};"
        : "+f"(c[0]), "+f"(c[1]), "+f"(c[2]), "+f"(c[3])
        : "r"(a[0]), "r"(a[1]), "r"(a[2]), "r"(a[3]), "r"(b0), "r"(b1));
}
__device__ __forceinline__ __half2 u2h(uint32_t u) {
    return *reinterpret_cast<__half2*>(&u);
}
__device__ __forceinline__ float sig_fast(float x) {
    float r;
    asm("rcp.approx.f32 %0, %1;" : "=f"(r) : "f"(1.f + __expf(-x)));
    return r;
}
__device__ __forceinline__ float tanh_fast(float x) {
    float r;
    asm("rcp.approx.f32 %0, %1;" : "=f"(r) : "f"(1.f + __expf(-2.f * x)));
    return fmaf(2.f, r, -1.f);
}

// ============================================================================
// Kernel 0: fp32 -> fp16 conversion (x and W_ih)
// ============================================================================
__global__ void __launch_bounds__(256)
f2h_kernel(const float* __restrict__ src, __half* __restrict__ dst, int n)
{
    int i = (blockIdx.x * 256 + threadIdx.x) * 8;
    if (i >= n) return;
    const float4 a = *(const float4*)(src + i);
    const float4 b = *(const float4*)(src + i + 4);
    __half2 h0 = __floats2half2_rn(a.x, a.y);
    __half2 h1 = __floats2half2_rn(a.z, a.w);
    __half2 h2 = __floats2half2_rn(b.x, b.y);
    __half2 h3 = __floats2half2_rn(b.z, b.w);
    uint4 o;
    o.x = *(uint32_t*)&h0; o.y = *(uint32_t*)&h1;
    o.z = *(uint32_t*)&h2; o.w = *(uint32_t*)&h3;
    *(uint4*)(dst + i) = o;
}

// ============================================================================
// Kernel 1: xg = x @ W_ih^T + b_ih + b_hh  via mma.sync.m16n8k16 (fp16->fp32).
// 128x128 tile / CTA, 8 warps of 64x32, 4-stage cp.async pipeline over K.
// ============================================================================
__global__ void __launch_bounds__(256, 1)
gemm_xg_mma(const float* __restrict__ b1, const float* __restrict__ b2)
{
    extern __shared__ char dynsmem[];
    __shared__ float s_bias[BN];

    const int tid    = threadIdx.x;
    const int lane   = tid & 31;
    const int wid    = tid >> 5;
    const int warp_m = wid >> 2;            // 0..1
    const int warp_n = wid & 3;             // 0..3
    const int mw     = warp_m * 64;
    const int nb     = warp_n * 32;
    const int n0     = blockIdx.x * BN;
    const int m0     = blockIdx.y * BM;

    const uint32_t sm0 = smem_u32(dynsmem);

    if (tid < BN) s_bias[tid] = b1[n0 + tid] + b2[n0 + tid];

    const __half* gA = g_xh + (size_t)m0 * IDIM;
    const __half* gB = g_wh + (size_t)n0 * IDIM;

    auto load_chunk = [&](int kc) {
        const uint32_t base = sm0 + (uint32_t)(kc & (STAGES - 1)) * STG_B;
        const int k0 = kc * BK;
#pragma unroll
        for (int part = 0; part < 4; ++part) {
            const int idx = part * 256 + tid;           // 0..1023
            const int row = (idx >> 2) & 127;
            const int seg = idx & 3;
            const uint32_t doff = (uint32_t)(row * (APAD * 2) + seg * 16);
            if (idx < 512)
                cp_async16(base + doff, gA + (size_t)row * IDIM + k0 + seg * 8);
            else
                cp_async16(base + STG_A + doff, gB + (size_t)row * IDIM + k0 + seg * 8);
        }
        asm volatile("cp.async.commit_group;" ::: "memory");
    };

    float acc[4][4][4];
#pragma unroll
    for (int mi = 0; mi < 4; ++mi)
#pragma unroll
        for (int ni = 0; ni < 4; ++ni)
#pragma unroll
            for (int q = 0; q < 4; ++q) acc[mi][ni][q] = 0.f;

    load_chunk(0);
    load_chunk(1);
    load_chunk(2);

    for (int kc = 0; kc < NCH; ++kc) {
        const int pf = kc + STAGES - 1;
        if (pf < NCH) load_chunk(pf);

        if (kc <= NCH - STAGES)
            asm volatile("cp.async.wait_group %0;" :: "n"(STAGES - 1) : "memory");
        else if (kc == NCH - 3)
            asm volatile("cp.async.wait_group 2;" ::: "memory");
        else if (kc == NCH - 2)
            asm volatile("cp.async.wait_group 1;" ::: "memory");
        else
            asm volatile("cp.async.wait_group 0;" ::: "memory");
        __syncthreads();

        const uint32_t as_ = sm0 + (uint32_t)(kc & (STAGES - 1)) * STG_B;
        const uint32_t bs_ = as_ + STG_A;

#pragma unroll
        for (int s = 0; s < 2; ++s) {               // two k16 steps
            uint32_t af[4][4];
#pragma unroll
            for (int mi = 0; mi < 4; ++mi) {
                const uint32_t addr = as_
                    + (uint32_t)(mw + mi * 16 + (lane & 15)) * (APAD * 2)
                    + (uint32_t)(s * 16 + ((lane >> 4) << 3)) * 2;
                ldmatrix_x4(af[mi], addr);
            }
            uint32_t bf[2][4];
#pragma unroll
            for (int g = 0; g < 2; ++g) {
                const uint32_t addr = bs_
                    + (uint32_t)(nb + g * 16 + (lane & 7) + (((lane >> 4) & 1) << 3)) * (APAD * 2)
                    + (uint32_t)(s * 16 + (((lane >> 3) & 1) << 3)) * 2;
                ldmatrix_x4(bf[g], addr);
            }
#pragma unroll
            for (int mi = 0; mi < 4; ++mi)
#pragma unroll
                for (int ni = 0; ni < 4; ++ni)
                    mma16816(acc[mi][ni], af[mi],
                             bf[ni >> 1][(ni & 1) * 2],
                             bf[ni >> 1][(ni & 1) * 2 + 1]);
        }
        __syncthreads();
    }

#pragma unroll
    for (int mi = 0; mi < 4; ++mi) {
        const int r0 = m0 + mw + mi * 16 + (lane >> 2);
#pragma unroll
        for (int ni = 0; ni < 4; ++ni) {
            const int c = nb + ni * 8 + (lane & 3) * 2;
            const float bb0 = s_bias[c];
            const float bb1 = s_bias[c + 1];
            float2 v0, v1;
            v0.x = acc[mi][ni][0] + bb0; v0.y = acc[mi][ni][1] + bb1;
            v1.x = acc[mi][ni][2] + bb0; v1.y = acc[mi][ni][3] + bb1;
            *(float2*)&g_xg[(size_t)r0 * GROWS + n0 + c]       = v0;
            *(float2*)&g_xg[(size_t)(r0 + 8) * GROWS + n0 + c] = v1;
        }
    }
}

// ============================================================================
// Kernel 2: persistent LSTM recurrence, 32 warps = 4 k-groups x 8 row-groups.
// Round-11 skeleton; changes: fp16 h broadcast (no cvts on critical path,
// half the h bytes) + red.release arrival (no ATOMG return, no producer
// membar). Consumer spin + threadfence/IVALL unchanged (proven).
// ============================================================================
__global__ void __launch_bounds__(RTHREADS, 1)
lstm_persistent(const float* __restrict__ W_hh)
{
    extern __shared__ __half sw[];
    __shared__ float4 s_part[MAXROWS];    // [row] -> 4 kgrp partials
    __shared__ float  s_c[UPC];

    const int tid   = threadIdx.x;
    const int wid   = tid >> 5;
    const int lane  = tid & 31;
    const int kgrp  = wid >> 3;           // 0..3
    const int rgrp  = wid & 7;            // 0..7
    const int cta   = blockIdx.x;
    const int u0    = cta * UPC;
    const int nu    = (HDIM - u0 < UPC) ? (HDIM - u0) : UPC;
    const int nrows = 4 * nu;
    const int koff  = kgrp * 512 + lane * 8;   // halves

    // one-time: W_hh rows -> SMEM fp16
    for (int e = tid * 4; e < nrows * HDIM; e += RTHREADS * 4) {
        int r    = e / HDIM;
        int k    = e - r * HDIM;
        int gate = r / nu;
        int u    = r - gate * nu;
        const float4 v = *(const float4*)&W_hh[(size_t)(gate * HDIM + u0 + u) * HDIM + k];
        __half2* dst = (__half2*)&sw[r * HDIM + k];
        dst[0] = __floats2half2_rn(v.x, v.y);
        dst[1] = __floats2half2_rn(v.z, v.w);
    }
    if (tid < UPC)     s_c[tid]    = 0.f;
    if (tid < MAXROWS) s_part[tid] = make_float4(0.f, 0.f, 0.f, 0.f);

    unsigned base = 0u;
    if (tid == 0) base = *(volatile unsigned*)&g_base;
    __syncthreads();

    for (int t = 0; t < SEQ; ++t) {
        // prefetch xg (independent of h)
        float xgv0 = 0.f, xgv1 = 0.f, xgv2 = 0.f, xgv3 = 0.f;
        if (tid < nu) {
            const float* xp = g_xg + (size_t)t * GROWS + u0 + tid;
            xgv0 = xp[0 * HDIM];
            xgv1 = xp[1 * HDIM];
            xgv2 = xp[2 * HDIM];
            xgv3 = xp[3 * HDIM];
        }

        if (t > 0) {
            __syncthreads();   // (A) step t-1 h stores done CTA-wide
            if (tid == 0) {
                const unsigned tgt = base + (unsigned)NCTA * (unsigned)t;
                // release-arrival: cumulative, orders the CTA's h stores
                // (write-through to L2) before the counter increment.
                asm volatile("red.release.gpu.global.add.u32 [%0], %1;"
                             :: "l"(&g_bar), "r"(1u) : "memory");
                while ((int)(*(volatile unsigned*)&g_bar - tgt) < 0) { }
                __threadfence();                       // acquire + IVALL: fresh L1
            }
            __syncthreads();   // (B)

            // h slice for this warp's k-range: 16 halves = 2 uint4 loads,
            // straight into HFMA2 operands (no conversion)
            const __half* hb = g_hh[t & 1];
            const uint4 hu0 = *(const uint4*)&hb[koff];         // halves 0..7
            const uint4 hu1 = *(const uint4*)&hb[koff + 256];   // halves 8..15
            const __half2 hh0 = u2h(hu0.x), hh1 = u2h(hu0.y);
            const __half2 hh2 = u2h(hu0.z), hh3 = u2h(hu0.w);
            const __half2 hh4 = u2h(hu1.x), hh5 = u2h(hu1.y);
            const __half2 hh6 = u2h(hu1.z), hh7 = u2h(hu1.w);

            for (int r = rgrp; r < nrows; r += 8) {
                const __half* wr = sw + r * HDIM + koff;
                const uint4 wv0 = *(const uint4*)(wr);
                const uint4 wv1 = *(const uint4*)(wr + 256);
                __half2 a0 = __hmul2(u2h(wv0.x), hh0);
                a0 = __hfma2(u2h(wv0.y), hh1, a0);
                __half2 a1 = __hmul2(u2h(wv0.z), hh2);
                a1 = __hfma2(u2h(wv0.w), hh3, a1);
                __half2 a2 = __hmul2(u2h(wv1.x), hh4);
                a2 = __hfma2(u2h(wv1.y), hh5, a2);
                __half2 a3 = __hmul2(u2h(wv1.z), hh6);
                a3 = __hfma2(u2h(wv1.w), hh7, a3);
                const float2 f0 = __half22float2(a0);
                const float2 f1 = __half22float2(a1);
                const float2 f2 = __half22float2(a2);
                const float2 f3 = __half22float2(a3);
                float acc = ((f0.x + f0.y) + (f1.x + f1.y))
                          + ((f2.x + f2.y) + (f3.x + f3.y));
#pragma unroll
                for (int off = 16; off; off >>= 1)
                    acc += __shfl_xor_sync(0xffffffffu, acc, off);
                if (lane == 0) ((float*)&s_part[r])[kgrp] = acc;
            }
        }
        __syncthreads();       // (C) s_part complete

        if (tid < nu) {
            const float4 pi = s_part[0 * nu + tid];
            const float4 pf = s_part[1 * nu + tid];
            const float4 pg = s_part[2 * nu + tid];
            const float4 po = s_part[3 * nu + tid];
            const float gi = xgv0 + (pi.x + pi.y) + (pi.z + pi.w);
            const float gf = xgv1 + (pf.x + pf.y) + (pf.z + pf.w);
            const float gg = xgv2 + (pg.x + pg.y) + (pg.z + pg.w);
            const float go = xgv3 + (po.x + po.y) + (po.z + po.w);
            const float ig = sig_fast(gi);
            const float fg = sig_fast(gf);
            const float g2 = tanh_fast(gg);
            const float og = sig_fast(go);
            const float cc = fg * s_c[tid] + ig * g2;
            s_c[tid] = cc;
            const float hv = og * tanh_fast(cc);
            g_h[(t + 1) & 1][u0 + tid]  = hv;                    // for final FC
            g_hh[(t + 1) & 1][u0 + tid] = __float2half_rn(hv);   // broadcast copy
        }
    }

    // final barrier: safe epoch-base update for the next graph replay
    __syncthreads();
    if (tid == 0) {
        __threadfence();
        atomicAdd(&g_bar, 1u);
        unsigned tgt = base + (unsigned)NCTA * (unsigned)SEQ;
        while ((int)(*(volatile unsigned*)&g_bar - tgt) < 0) { }
        if (cta == 0) *(volatile unsigned*)&g_base = tgt;
    }
}

// ============================================================================
// Kernel 3: out = h_last @ W_fc^T + b_fc   (h_last in g_h[0]; SEQ even)
// ============================================================================
__global__ void __launch_bounds__(256)
fc_kernel(const float* __restrict__ Wfc, const float* __restrict__ bfc,
          float* __restrict__ out)
{
    const int o    = blockIdx.x * 8 + (threadIdx.x >> 5);
    const int lane = threadIdx.x & 31;
    const float* hb = g_h[0];
    const float* wr = Wfc + (size_t)o * HDIM;
    float acc = 0.f;
#pragma unroll
    for (int i = 0; i < 16; ++i) {
        const int k = i * 128 + lane * 4;
        const float4 w  = *(const float4*)&wr[k];
        const float4 h4 = *(const float4*)&hb[k];
        acc += w.x * h4.x + w.y * h4.y + w.z * h4.z + w.w * h4.w;
    }
#pragma unroll
    for (int off = 16; off; off >>= 1)
        acc += __shfl_xor_sync(0xffffffffu, acc, off);
    if (lane == 0) out[o] = acc + bfc[o];
}

// ============================================================================
extern "C" void kernel_launch(void* const* d_in, const int* in_sizes, int n_in,
                              void* d_out, int out_size)
{
    const float* x   = (const float*)d_in[0];
    const float* Wih = (const float*)d_in[1];
    const float* Whh = (const float*)d_in[2];
    const float* bih = (const float*)d_in[3];
    const float* bhh = (const float*)d_in[4];
    const float* Wfc = (const float*)d_in[5];
    const float* bfc = (const float*)d_in[6];
    float* out = (float*)d_out;

    static __half* p_xh = nullptr;
    static __half* p_wh = nullptr;
    if (!p_xh) {
        cudaGetSymbolAddress((void**)&p_xh, g_xh);
        cudaGetSymbolAddress((void**)&p_wh, g_wh);
        cudaFuncSetAttribute(gemm_xg_mma,
                             cudaFuncAttributeMaxDynamicSharedMemorySize,
                             (int)GEMM_SMEM);
        cudaFuncSetAttribute(lstm_persistent,
                             cudaFuncAttributeMaxDynamicSharedMemorySize,
                             (int)SW_BYTES);
    }

    f2h_kernel<<<(SEQ * IDIM / 8 + 255) / 256, 256>>>(x, p_xh, SEQ * IDIM);
    f2h_kernel<<<(GROWS * IDIM / 8 + 255) / 256, 256>>>(Wih, p_wh, GROWS * IDIM);
    gemm_xg_mma<<<dim3(GROWS / BN, SEQ / BM), 256, GEMM_SMEM>>>(bih, bhh);
    lstm_persistent<<<NCTA, RTHREADS, SW_BYTES>>>(Whh);
    fc_kernel<<<OUTD / 8, 256>>>(Wfc, bfc, out);
}

// round 15
// speedup vs baseline: 1.7841x; 1.0416x over previous
#include <cuda_runtime.h>
#include <cuda_fp16.h>
#include <math.h>
#include <stdint.h>

// Problem dims
#define SEQ    4096
#define IDIM   2048
#define HDIM   2048
#define GROWS  8192   // 4*HDIM, PyTorch gate order i,f,g,o
#define OUTD   2048

// Persistent recurrence kernel config
#define UPC      14
#define NCTA     147
#define RTHREADS 1024             // 32 warps: 4 k-groups x 8 row-groups
#define MAXROWS  (4*UPC)
#define SW_BYTES (MAXROWS*HDIM*sizeof(__half))   // 229376 B

// mma.sync GEMM config
#define BM 128
#define BN 128
#define BK 32
#define NCH    (IDIM/BK)          // 64 k-chunks
#define STAGES 4
#define APAD   40                 // halves per SMEM row (32 + 8 pad) -> 80B stride
#define STG_A  (BM*APAD*2)        // 10240 B
#define STG_B  (2*STG_A)          // 20480 B per stage (A then B)
#define GEMM_SMEM (STAGES*STG_B)  // 81920 B

// -------- device scratch (static allocation only) --------
__device__ float    g_xg[(size_t)SEQ * GROWS];   // 128 MB
__device__ __half   g_xh[(size_t)SEQ * IDIM];    // 16 MB  x in fp16
__device__ __half   g_wh[(size_t)GROWS * IDIM];  // 32 MB  W_ih in fp16
__device__ float    g_h[2][HDIM];                // fp32 h (final FC reads this)
__device__ __half   g_hh[2][HDIM];               // fp16 h broadcast copy
__device__ unsigned g_bar  = 0u;                 // monotonic arrival counter
__device__ unsigned g_base = 0u;                 // epoch base across graph replays

// ---------------- PTX helpers (all sm_80+; no arch-suffix features) ----------
__device__ __forceinline__ uint32_t smem_u32(const void* p) {
    return (uint32_t)__cvta_generic_to_shared(p);
}
__device__ __forceinline__ void cp_async16(uint32_t dst, const void* src) {
    asm volatile("cp.async.cg.shared.global [%0], [%1], 16;" :: "r"(dst), "l"(src));
}
__device__ __forceinline__ void ldmatrix_x4(uint32_t* r, uint32_t addr) {
    asm volatile("ldmatrix.sync.aligned.m8n8.x4.shared.b16 {%0,%1,%2,%3}, [%4];"
                 : "=r"(r[0]), "=r"(r[1]), "=r"(r[2]), "=r"(r[3]) : "r"(addr));
}
__device__ __forceinline__ void mma16816(float* c, const uint32_t* a,
                                         uint32_t b0, uint32_t b1) {
    asm volatile(
        "mma.sync.aligned.m16n8k16.row.col.f32.f16.f16.f32 "
        "{%0,%1,%2,%3}, {%4,%5,%6,%7}, {%8,%9}, {%0,%1,%2,%3};"
        : "+f"(c[0]), "+f"(c[1]), "+f"(c[2]), "+f"(c[3])
        : "r"(a[0]), "r"(a[1]), "r"(a[2]), "r"(a[3]), "r"(b0), "r"(b1));
}
__device__ __forceinline__ __half2 u2h(uint32_t u) {
    return *reinterpret_cast<__half2*>(&u);
}
__device__ __forceinline__ float sig_fast(float x) {
    float r;
    asm("rcp.approx.f32 %0, %1;" : "=f"(r) : "f"(1.f + __expf(-x)));
    return r;
}
__device__ __forceinline__ float tanh_fast(float x) {
    float r;
    asm("rcp.approx.f32 %0, %1;" : "=f"(r) : "f"(1.f + __expf(-2.f * x)));
    return fmaf(2.f, r, -1.f);
}

// ============================================================================
// Kernel 0: fp32 -> fp16 conversion (x and W_ih)
// ============================================================================
__global__ void __launch_bounds__(256)
f2h_kernel(const float* __restrict__ src, __half* __restrict__ dst, int n)
{
    int i = (blockIdx.x * 256 + threadIdx.x) * 8;
    if (i >= n) return;
    const float4 a = *(const float4*)(src + i);
    const float4 b = *(const float4*)(src + i + 4);
    __half2 h0 = __floats2half2_rn(a.x, a.y);
    __half2 h1 = __floats2half2_rn(a.z, a.w);
    __half2 h2 = __floats2half2_rn(b.x, b.y);
    __half2 h3 = __floats2half2_rn(b.z, b.w);
    uint4 o;
    o.x = *(uint32_t*)&h0; o.y = *(uint32_t*)&h1;
    o.z = *(uint32_t*)&h2; o.w = *(uint32_t*)&h3;
    *(uint4*)(dst + i) = o;
}

// ============================================================================
// Kernel 1: xg = x @ W_ih^T + b_ih + b_hh  via mma.sync.m16n8k16 (fp16->fp32).
// 128x128 tile / CTA, 8 warps of 64x32, 4-stage cp.async pipeline over K.
// ============================================================================
__global__ void __launch_bounds__(256, 1)
gemm_xg_mma(const float* __restrict__ b1, const float* __restrict__ b2)
{
    extern __shared__ char dynsmem[];
    __shared__ float s_bias[BN];

    const int tid    = threadIdx.x;
    const int lane   = tid & 31;
    const int wid    = tid >> 5;
    const int warp_m = wid >> 2;            // 0..1
    const int warp_n = wid & 3;             // 0..3
    const int mw     = warp_m * 64;
    const int nb     = warp_n * 32;
    const int n0     = blockIdx.x * BN;
    const int m0     = blockIdx.y * BM;

    const uint32_t sm0 = smem_u32(dynsmem);

    if (tid < BN) s_bias[tid] = b1[n0 + tid] + b2[n0 + tid];

    const __half* gA = g_xh + (size_t)m0 * IDIM;
    const __half* gB = g_wh + (size_t)n0 * IDIM;

    auto load_chunk = [&](int kc) {
        const uint32_t base = sm0 + (uint32_t)(kc & (STAGES - 1)) * STG_B;
        const int k0 = kc * BK;
#pragma unroll
        for (int part = 0; part < 4; ++part) {
            const int idx = part * 256 + tid;           // 0..1023
            const int row = (idx >> 2) & 127;
            const int seg = idx & 3;
            const uint32_t doff = (uint32_t)(row * (APAD * 2) + seg * 16);
            if (idx < 512)
                cp_async16(base + doff, gA + (size_t)row * IDIM + k0 + seg * 8);
            else
                cp_async16(base + STG_A + doff, gB + (size_t)row * IDIM + k0 + seg * 8);
        }
        asm volatile("cp.async.commit_group;" ::: "memory");
    };

    float acc[4][4][4];
#pragma unroll
    for (int mi = 0; mi < 4; ++mi)
#pragma unroll
        for (int ni = 0; ni < 4; ++ni)
#pragma unroll
            for (int q = 0; q < 4; ++q) acc[mi][ni][q] = 0.f;

    load_chunk(0);
    load_chunk(1);
    load_chunk(2);

    for (int kc = 0; kc < NCH; ++kc) {
        const int pf = kc + STAGES - 1;
        if (pf < NCH) load_chunk(pf);

        if (kc <= NCH - STAGES)
            asm volatile("cp.async.wait_group %0;" :: "n"(STAGES - 1) : "memory");
        else if (kc == NCH - 3)
            asm volatile("cp.async.wait_group 2;" ::: "memory");
        else if (kc == NCH - 2)
            asm volatile("cp.async.wait_group 1;" ::: "memory");
        else
            asm volatile("cp.async.wait_group 0;" ::: "memory");
        __syncthreads();

        const uint32_t as_ = sm0 + (uint32_t)(kc & (STAGES - 1)) * STG_B;
        const uint32_t bs_ = as_ + STG_A;

#pragma unroll
        for (int s = 0; s < 2; ++s) {               // two k16 steps
            uint32_t af[4][4];
#pragma unroll
            for (int mi = 0; mi < 4; ++mi) {
                const uint32_t addr = as_
                    + (uint32_t)(mw + mi * 16 + (lane & 15)) * (APAD * 2)
                    + (uint32_t)(s * 16 + ((lane >> 4) << 3)) * 2;
                ldmatrix_x4(af[mi], addr);
            }
            uint32_t bf[2][4];
#pragma unroll
            for (int g = 0; g < 2; ++g) {
                const uint32_t addr = bs_
                    + (uint32_t)(nb + g * 16 + (lane & 7) + (((lane >> 4) & 1) << 3)) * (APAD * 2)
                    + (uint32_t)(s * 16 + (((lane >> 3) & 1) << 3)) * 2;
                ldmatrix_x4(bf[g], addr);
            }
#pragma unroll
            for (int mi = 0; mi < 4; ++mi)
#pragma unroll
                for (int ni = 0; ni < 4; ++ni)
                    mma16816(acc[mi][ni], af[mi],
                             bf[ni >> 1][(ni & 1) * 2],
                             bf[ni >> 1][(ni & 1) * 2 + 1]);
        }
        __syncthreads();
    }

#pragma unroll
    for (int mi = 0; mi < 4; ++mi) {
        const int r0 = m0 + mw + mi * 16 + (lane >> 2);
#pragma unroll
        for (int ni = 0; ni < 4; ++ni) {
            const int c = nb + ni * 8 + (lane & 3) * 2;
            const float bb0 = s_bias[c];
            const float bb1 = s_bias[c + 1];
            float2 v0, v1;
            v0.x = acc[mi][ni][0] + bb0; v0.y = acc[mi][ni][1] + bb1;
            v1.x = acc[mi][ni][2] + bb0; v1.y = acc[mi][ni][3] + bb1;
            *(float2*)&g_xg[(size_t)r0 * GROWS + n0 + c]       = v0;
            *(float2*)&g_xg[(size_t)(r0 + 8) * GROWS + n0 + c] = v1;
        }
    }
}

// ============================================================================
// Kernel 2: persistent LSTM recurrence, 32 warps = 4 k-groups x 8 row-groups.
// Round-14 skeleton; changes: (1) fully-unrolled 7-row path for nu==UPC with
// interleaved shfl trees, (2) barrier (A) removed -- gate lives in warp 0, so
// a __syncwarp orders its h stores before the release-arrival, issued at the
// end of each step's gate. Consumer spin + threadfence/IVALL unchanged.
// ============================================================================
__global__ void __launch_bounds__(RTHREADS, 1)
lstm_persistent(const float* __restrict__ W_hh)
{
    extern __shared__ __half sw[];
    __shared__ float4 s_part[MAXROWS];    // [row] -> 4 kgrp partials
    __shared__ float  s_c[UPC];

    const int tid   = threadIdx.x;
    const int wid   = tid >> 5;
    const int lane  = tid & 31;
    const int kgrp  = wid >> 3;           // 0..3
    const int rgrp  = wid & 7;            // 0..7
    const int cta   = blockIdx.x;
    const int u0    = cta * UPC;
    const int nu    = (HDIM - u0 < UPC) ? (HDIM - u0) : UPC;
    const int nrows = 4 * nu;
    const int koff  = kgrp * 512 + lane * 8;   // halves

    // one-time: W_hh rows -> SMEM fp16
    for (int e = tid * 4; e < nrows * HDIM; e += RTHREADS * 4) {
        int r    = e / HDIM;
        int k    = e - r * HDIM;
        int gate = r / nu;
        int u    = r - gate * nu;
        const float4 v = *(const float4*)&W_hh[(size_t)(gate * HDIM + u0 + u) * HDIM + k];
        __half2* dst = (__half2*)&sw[r * HDIM + k];
        dst[0] = __floats2half2_rn(v.x, v.y);
        dst[1] = __floats2half2_rn(v.z, v.w);
    }
    if (tid < UPC)     s_c[tid]    = 0.f;
    if (tid < MAXROWS) s_part[tid] = make_float4(0.f, 0.f, 0.f, 0.f);

    unsigned base = 0u;
    if (tid == 0) base = *(volatile unsigned*)&g_base;
    __syncthreads();

    for (int t = 0; t < SEQ; ++t) {
        // prefetch xg (independent of h)
        float xgv0 = 0.f, xgv1 = 0.f, xgv2 = 0.f, xgv3 = 0.f;
        if (tid < nu) {
            const float* xp = g_xg + (size_t)t * GROWS + u0 + tid;
            xgv0 = xp[0 * HDIM];
            xgv1 = xp[1 * HDIM];
            xgv2 = xp[2 * HDIM];
            xgv3 = xp[3 * HDIM];
        }

        if (t > 0) {
            // arrival for this barrier was issued at the end of step t-1's gate
            if (tid == 0) {
                const unsigned tgt = base + (unsigned)NCTA * (unsigned)t;
                while ((int)(*(volatile unsigned*)&g_bar - tgt) < 0) { }
                __threadfence();                       // acquire + IVALL: fresh L1
            }
            __syncthreads();   // (B)

            // h slice for this warp's k-range: 16 halves = 2 uint4 loads,
            // straight into HFMA2 operands (no conversion)
            const __half* hb = g_hh[t & 1];
            const uint4 hu0 = *(const uint4*)&hb[koff];         // halves 0..7
            const uint4 hu1 = *(const uint4*)&hb[koff + 256];   // halves 8..15
            const __half2 hh0 = u2h(hu0.x), hh1 = u2h(hu0.y);
            const __half2 hh2 = u2h(hu0.z), hh3 = u2h(hu0.w);
            const __half2 hh4 = u2h(hu1.x), hh5 = u2h(hu1.y);
            const __half2 hh6 = u2h(hu1.z), hh7 = u2h(hu1.w);

            if (nu == UPC) {
                // ---- fully unrolled: 7 rows, interleaved reduction trees ----
                float accs[7];
                const __half* wbase = sw + rgrp * HDIM + koff;
#pragma unroll
                for (int i = 0; i < 7; ++i) {
                    const __half* wr = wbase + i * 8 * HDIM;
                    const uint4 wv0 = *(const uint4*)(wr);
                    const uint4 wv1 = *(const uint4*)(wr + 256);
                    __half2 a0 = __hmul2(u2h(wv0.x), hh0);
                    a0 = __hfma2(u2h(wv0.y), hh1, a0);
                    __half2 a1 = __hmul2(u2h(wv0.z), hh2);
                    a1 = __hfma2(u2h(wv0.w), hh3, a1);
                    __half2 a2 = __hmul2(u2h(wv1.x), hh4);
                    a2 = __hfma2(u2h(wv1.y), hh5, a2);
                    __half2 a3 = __hmul2(u2h(wv1.z), hh6);
                    a3 = __hfma2(u2h(wv1.w), hh7, a3);
                    const float2 f0 = __half22float2(a0);
                    const float2 f1 = __half22float2(a1);
                    const float2 f2 = __half22float2(a2);
                    const float2 f3 = __half22float2(a3);
                    accs[i] = ((f0.x + f0.y) + (f1.x + f1.y))
                            + ((f2.x + f2.y) + (f3.x + f3.y));
                }
#pragma unroll
                for (int off = 16; off; off >>= 1) {
#pragma unroll
                    for (int i = 0; i < 7; ++i)
                        accs[i] += __shfl_xor_sync(0xffffffffu, accs[i], off);
                }
                if (lane == 0) {
#pragma unroll
                    for (int i = 0; i < 7; ++i)
                        ((float*)&s_part[rgrp + i * 8])[kgrp] = accs[i];
                }
            } else {
                // ---- generic path (last CTA only) ----
                for (int r = rgrp; r < nrows; r += 8) {
                    const __half* wr = sw + r * HDIM + koff;
                    const uint4 wv0 = *(const uint4*)(wr);
                    const uint4 wv1 = *(const uint4*)(wr + 256);
                    __half2 a0 = __hmul2(u2h(wv0.x), hh0);
                    a0 = __hfma2(u2h(wv0.y), hh1, a0);
                    __half2 a1 = __hmul2(u2h(wv0.z), hh2);
                    a1 = __hfma2(u2h(wv0.w), hh3, a1);
                    __half2 a2 = __hmul2(u2h(wv1.x), hh4);
                    a2 = __hfma2(u2h(wv1.y), hh5, a2);
                    __half2 a3 = __hmul2(u2h(wv1.z), hh6);
                    a3 = __hfma2(u2h(wv1.w), hh7, a3);
                    const float2 f0 = __half22float2(a0);
                    const float2 f1 = __half22float2(a1);
                    const float2 f2 = __half22float2(a2);
                    const float2 f3 = __half22float2(a3);
                    float acc = ((f0.x + f0.y) + (f1.x + f1.y))
                              + ((f2.x + f2.y) + (f3.x + f3.y));
#pragma unroll
                    for (int off = 16; off; off >>= 1)
                        acc += __shfl_xor_sync(0xffffffffu, acc, off);
                    if (lane == 0) ((float*)&s_part[r])[kgrp] = acc;
                }
            }
        }
        __syncthreads();       // (C) s_part complete

        if (tid < nu) {
            const float4 pi = s_part[0 * nu + tid];
            const float4 pf = s_part[1 * nu + tid];
            const float4 pg = s_part[2 * nu + tid];
            const float4 po = s_part[3 * nu + tid];
            const float gi = xgv0 + (pi.x + pi.y) + (pi.z + pi.w);
            const float gf = xgv1 + (pf.x + pf.y) + (pf.z + pf.w);
            const float gg = xgv2 + (pg.x + pg.y) + (pg.z + pg.w);
            const float go = xgv3 + (po.x + po.y) + (po.z + po.w);
            const float ig = sig_fast(gi);
            const float fg = sig_fast(gf);
            const float g2 = tanh_fast(gg);
            const float og = sig_fast(go);
            const float cc = fg * s_c[tid] + ig * g2;
            s_c[tid] = cc;
            const float hv = og * tanh_fast(cc);
            g_h[(t + 1) & 1][u0 + tid]  = hv;                    // for final FC
            g_hh[(t + 1) & 1][u0 + tid] = __float2half_rn(hv);   // broadcast copy
        }
        // early release-arrival: gate threads are all in warp 0, so a warp
        // sync orders their h stores before the cumulative release-arrive.
        // (C) + release order the other warps' step-t reads as well.
        if (wid == 0) {
            __syncwarp();
            if (lane == 0)
                asm volatile("red.release.gpu.global.add.u32 [%0], %1;"
                             :: "l"(&g_bar), "r"(1u) : "memory");
        }
    }

    // epilogue: arrivals total SEQ per CTA; wait for all, then update epoch
    if (tid == 0) {
        const unsigned tgt = base + (unsigned)NCTA * (unsigned)SEQ;
        while ((int)(*(volatile unsigned*)&g_bar - tgt) < 0) { }
        if (cta == 0) *(volatile unsigned*)&g_base = tgt;
    }
}

// ============================================================================
// Kernel 3: out = h_last @ W_fc^T + b_fc   (h_last in g_h[0]; SEQ even)
// ============================================================================
__global__ void __launch_bounds__(256)
fc_kernel(const float* __restrict__ Wfc, const float* __restrict__ bfc,
          float* __restrict__ out)
{
    const int o    = blockIdx.x * 8 + (threadIdx.x >> 5);
    const int lane = threadIdx.x & 31;
    const float* hb = g_h[0];
    const float* wr = Wfc + (size_t)o * HDIM;
    float acc = 0.f;
#pragma unroll
    for (int i = 0; i < 16; ++i) {
        const int k = i * 128 + lane * 4;
        const float4 w  = *(const float4*)&wr[k];
        const float4 h4 = *(const float4*)&hb[k];
        acc += w.x * h4.x + w.y * h4.y + w.z * h4.z + w.w * h4.w;
    }
#pragma unroll
    for (int off = 16; off; off >>= 1)
        acc += __shfl_xor_sync(0xffffffffu, acc, off);
    if (lane == 0) out[o] = acc + bfc[o];
}

// ============================================================================
extern "C" void kernel_launch(void* const* d_in, const int* in_sizes, int n_in,
                              void* d_out, int out_size)
{
    const float* x   = (const float*)d_in[0];
    const float* Wih = (const float*)d_in[1];
    const float* Whh = (const float*)d_in[2];
    const float* bih = (const float*)d_in[3];
    const float* bhh = (const float*)d_in[4];
    const float* Wfc = (const float*)d_in[5];
    const float* bfc = (const float*)d_in[6];
    float* out = (float*)d_out;

    static __half* p_xh = nullptr;
    static __half* p_wh = nullptr;
    if (!p_xh) {
        cudaGetSymbolAddress((void**)&p_xh, g_xh);
        cudaGetSymbolAddress((void**)&p_wh, g_wh);
        cudaFuncSetAttribute(gemm_xg_mma,
                             cudaFuncAttributeMaxDynamicSharedMemorySize,
                             (int)GEMM_SMEM);
        cudaFuncSetAttribute(lstm_persistent,
                             cudaFuncAttributeMaxDynamicSharedMemorySize,
                             (int)SW_BYTES);
    }

    f2h_kernel<<<(SEQ * IDIM / 8 + 255) / 256, 256>>>(x, p_xh, SEQ * IDIM);
    f2h_kernel<<<(GROWS * IDIM / 8 + 255) / 256, 256>>>(Wih, p_wh, GROWS * IDIM);
    gemm_xg_mma<<<dim3(GROWS / BN, SEQ / BM), 256, GEMM_SMEM>>>(bih, bhh);
    lstm_persistent<<<NCTA, RTHREADS, SW_BYTES>>>(Whh);
    fc_kernel<<<OUTD / 8, 256>>>(Wfc, bfc, out);
}